// round 1
// baseline (speedup 1.0000x reference)
#include <cuda_runtime.h>
#include <math.h>

#define Bc 4
#define Sc 1024
#define Dc 512
#define Hc 8
#define DHc 64
#define DIc 2048
#define Lc 12
#define Vc 10000
#define M_ROWS (Bc*Sc)   /* 4096 */

// ---------------- scratch (no allocations allowed) ----------------
__device__ float g_h  [M_ROWS*Dc];
__device__ float g_q  [M_ROWS*Dc];
__device__ float g_k  [M_ROWS*Dc];
__device__ float g_v  [M_ROWS*Dc];
__device__ float g_ao [M_ROWS*Dc];
__device__ float g_tmp[M_ROWS*Dc];
__device__ float g_ff [M_ROWS*DIc];

// ---------------- embedding: h = word_emb[data] + pos_emb[:S] ----------------
__global__ void embed_kernel(const int* __restrict__ data,
                             const float* __restrict__ we,
                             const float* __restrict__ pe,
                             float* __restrict__ h) {
    int i = blockIdx.x * blockDim.x + threadIdx.x;
    if (i >= M_ROWS * Dc) return;
    int d   = i % Dc;
    int row = i / Dc;
    int s   = row % Sc;
    int tok = data[row];
    h[i] = we[(size_t)tok * Dc + d] + pe[(size_t)s * Dc + d];
}

// ---------------- SGEMM: C[M,N] = A[M,K] @ W[N,K]^T (+bias)(+res)(relu?) ----
__global__ __launch_bounds__(256) void sgemm_kernel(
    const float* __restrict__ A, const float* __restrict__ W,
    const float* __restrict__ bias, const float* __restrict__ res,
    float* __restrict__ C, int M, int N, int K, int doRelu)
{
    const int BM = 64, BN = 64, BK = 16;
    __shared__ float As[BK][BM];
    __shared__ float Bs[BK][BN];

    int tid = threadIdx.x;
    int tx = tid % 16, ty = tid / 16;

    int r    = tid >> 2;              // 0..63
    int kA   = (tid & 3) * 4;         // 0,4,8,12
    int rowA = blockIdx.y * BM + r;
    int colW = blockIdx.x * BN + r;

    float acc[4][4] = {};

    int KT = K / BK;                  // K is always a multiple of 16 here
    for (int t = 0; t < KT; t++) {
        int k0 = t * BK;
        float4 a4 = make_float4(0.f, 0.f, 0.f, 0.f);
        float4 b4 = make_float4(0.f, 0.f, 0.f, 0.f);
        if (rowA < M) a4 = *reinterpret_cast<const float4*>(A + (size_t)rowA * K + k0 + kA);
        if (colW < N) b4 = *reinterpret_cast<const float4*>(W + (size_t)colW * K + k0 + kA);
        As[kA+0][r] = a4.x; As[kA+1][r] = a4.y; As[kA+2][r] = a4.z; As[kA+3][r] = a4.w;
        Bs[kA+0][r] = b4.x; Bs[kA+1][r] = b4.y; Bs[kA+2][r] = b4.z; Bs[kA+3][r] = b4.w;
        __syncthreads();

        #pragma unroll
        for (int k = 0; k < BK; k++) {
            float a[4], b[4];
            #pragma unroll
            for (int i = 0; i < 4; i++) a[i] = As[k][ty*4 + i];
            #pragma unroll
            for (int j = 0; j < 4; j++) b[j] = Bs[k][tx*4 + j];
            #pragma unroll
            for (int i = 0; i < 4; i++)
                #pragma unroll
                for (int j = 0; j < 4; j++)
                    acc[i][j] += a[i] * b[j];
        }
        __syncthreads();
    }

    #pragma unroll
    for (int i = 0; i < 4; i++) {
        int row = blockIdx.y * BM + ty*4 + i;
        if (row >= M) continue;
        #pragma unroll
        for (int j = 0; j < 4; j++) {
            int col = blockIdx.x * BN + tx*4 + j;
            if (col >= N) continue;
            float vv = acc[i][j];
            if (bias) vv += bias[col];
            if (res)  vv += res[(size_t)row * N + col];
            if (doRelu) vv = fmaxf(vv, 0.f);
            C[(size_t)row * N + col] = vv;
        }
    }
}

// ---------------- causal attention: warp per (b,h,q), online softmax --------
__global__ void attn_kernel(const float* __restrict__ Q, const float* __restrict__ K,
                            const float* __restrict__ V, float* __restrict__ O) {
    int w = (blockIdx.x * blockDim.x + threadIdx.x) >> 5;
    int lane = threadIdx.x & 31;
    if (w >= Bc * Hc * Sc) return;
    int qi = w % Sc;
    int bh = w / Sc;
    int b  = bh / Hc, hh = bh % Hc;

    const float scale = 0.125f;  // 1/sqrt(64)
    const int HD = Hc * DHc;
    size_t qoff = ((size_t)(b * Sc + qi)) * HD + hh * DHc;
    float q0 = Q[qoff + lane]      * scale;
    float q1 = Q[qoff + lane + 32] * scale;

    float m = -1e30f, l = 0.f, a0 = 0.f, a1 = 0.f;
    size_t kbase = ((size_t)b * Sc) * HD + hh * DHc;
    for (int ki = 0; ki <= qi; ki++) {
        const float* kp = K + kbase + (size_t)ki * HD;
        float s = q0 * kp[lane] + q1 * kp[lane + 32];
        #pragma unroll
        for (int off = 16; off; off >>= 1) s += __shfl_xor_sync(0xffffffffu, s, off);

        float nm = fmaxf(m, s);
        float c  = __expf(m - nm);
        float p  = __expf(s - nm);
        const float* vp = V + kbase + (size_t)ki * HD;
        l  = l  * c + p;
        a0 = a0 * c + p * vp[lane];
        a1 = a1 * c + p * vp[lane + 32];
        m = nm;
    }
    float inv = 1.f / l;
    O[qoff + lane]      = a0 * inv;
    O[qoff + lane + 32] = a1 * inv;
}

// ---------------- LayerNorm over D=512, one block per row -------------------
__global__ void ln_kernel(const float* __restrict__ X, const float* __restrict__ g,
                          const float* __restrict__ bta, float* __restrict__ Y) {
    int row = blockIdx.x;
    const float* x = X + (size_t)row * Dc;
    float* y = Y + (size_t)row * Dc;
    int tid = threadIdx.x;     // 128 threads, each 4 elements

    float v[4];
    float sum = 0.f;
    #pragma unroll
    for (int i = 0; i < 4; i++) { v[i] = x[tid + i*128]; sum += v[i]; }

    __shared__ float red[4];
    #pragma unroll
    for (int off = 16; off; off >>= 1) sum += __shfl_xor_sync(0xffffffffu, sum, off);
    if ((tid & 31) == 0) red[tid >> 5] = sum;
    __syncthreads();
    sum = red[0] + red[1] + red[2] + red[3];
    float mean = sum * (1.f / Dc);

    float sq = 0.f;
    #pragma unroll
    for (int i = 0; i < 4; i++) { float d = v[i] - mean; sq += d * d; }
    __shared__ float red2[4];
    #pragma unroll
    for (int off = 16; off; off >>= 1) sq += __shfl_xor_sync(0xffffffffu, sq, off);
    if ((tid & 31) == 0) red2[tid >> 5] = sq;
    __syncthreads();
    sq = red2[0] + red2[1] + red2[2] + red2[3];
    float rstd = rsqrtf(sq * (1.f / Dc) + 1e-5f);

    #pragma unroll
    for (int i = 0; i < 4; i++) {
        int d = tid + i*128;
        y[d] = (v[i] - mean) * rstd * g[d] + bta[d];
    }
}

// ---------------- launch ----------------------------------------------------
extern "C" void kernel_launch(void* const* d_in, const int* in_sizes, int n_in,
                              void* d_out, int out_size) {
    const int*   data = (const int*)  d_in[0];
    const float* we   = (const float*)d_in[1];
    const float* pe   = (const float*)d_in[2];
    const float* Wq   = (const float*)d_in[3];
    const float* Wkv  = (const float*)d_in[4];
    const float* Wo   = (const float*)d_in[5];
    const float* g1   = (const float*)d_in[6];
    const float* bl1  = (const float*)d_in[7];
    const float* W1   = (const float*)d_in[8];
    const float* bf1  = (const float*)d_in[9];
    const float* W2   = (const float*)d_in[10];
    const float* bf2  = (const float*)d_in[11];
    const float* g2   = (const float*)d_in[12];
    const float* bl2  = (const float*)d_in[13];
    const float* outb = (const float*)d_in[14];
    float* out = (float*)d_out;

    float *h, *q, *k, *v, *ao, *tmp, *ff;
    cudaGetSymbolAddress((void**)&h,   g_h);
    cudaGetSymbolAddress((void**)&q,   g_q);
    cudaGetSymbolAddress((void**)&k,   g_k);
    cudaGetSymbolAddress((void**)&v,   g_v);
    cudaGetSymbolAddress((void**)&ao,  g_ao);
    cudaGetSymbolAddress((void**)&tmp, g_tmp);
    cudaGetSymbolAddress((void**)&ff,  g_ff);

    embed_kernel<<<(M_ROWS*Dc + 255)/256, 256>>>(data, we, pe, h);

    dim3 gsD ((Dc  + 63)/64, (M_ROWS + 63)/64);
    dim3 gsDI((DIc + 63)/64, (M_ROWS + 63)/64);
    dim3 gsV ((Vc  + 63)/64, (M_ROWS + 63)/64);

    for (int l = 0; l < Lc; l++) {
        const float* wq  = Wq  + (size_t)l * Dc * Dc;
        const float* wkv = Wkv + (size_t)l * 2 * Dc * Dc;
        const float* wo  = Wo  + (size_t)l * Dc * Dc;

        sgemm_kernel<<<gsD, 256>>>(h, wq,  nullptr, nullptr, q, M_ROWS, Dc, Dc, 0);
        sgemm_kernel<<<gsD, 256>>>(h, wkv, nullptr, nullptr, k, M_ROWS, Dc, Dc, 0);
        sgemm_kernel<<<gsD, 256>>>(h, wkv + (size_t)Dc * Dc, nullptr, nullptr, v, M_ROWS, Dc, Dc, 0);

        attn_kernel<<<(Bc*Hc*Sc*32)/128, 128>>>(q, k, v, ao);

        sgemm_kernel<<<gsD, 256>>>(ao, wo, nullptr, h, tmp, M_ROWS, Dc, Dc, 0);
        ln_kernel<<<M_ROWS, 128>>>(tmp, g1 + (size_t)l*Dc, bl1 + (size_t)l*Dc, h);

        sgemm_kernel<<<gsDI, 256>>>(h, W1 + (size_t)l*DIc*Dc, bf1 + (size_t)l*DIc, nullptr, ff, M_ROWS, DIc, Dc, 1);
        sgemm_kernel<<<gsD,  256>>>(ff, W2 + (size_t)l*Dc*DIc, bf2 + (size_t)l*Dc, h, tmp, M_ROWS, Dc, DIc, 0);
        ln_kernel<<<M_ROWS, 128>>>(tmp, g2 + (size_t)l*Dc, bl2 + (size_t)l*Dc, h);
    }

    sgemm_kernel<<<gsV, 256>>>(h, we, outb, nullptr, out, M_ROWS, Vc, Dc, 0);
}

// round 2
// speedup vs baseline: 3.5625x; 3.5625x over previous
#include <cuda_runtime.h>
#include <math.h>
#include <stdint.h>

#define Bc 4
#define Sc 1024
#define Dc 512
#define Hc 8
#define DHc 64
#define DIc 2048
#define Lc 12
#define Vc 10000
#define M_ROWS (Bc*Sc)   /* 4096 */

// ---------------- scratch (no allocations allowed) ----------------
__device__ float g_h  [M_ROWS*Dc];
__device__ float g_q  [M_ROWS*Dc];
__device__ float g_kv [M_ROWS*2*Dc];
__device__ float g_ao [M_ROWS*Dc];
__device__ float g_tmp[M_ROWS*Dc];
__device__ float g_ff [M_ROWS*DIc];

// ---------------- embedding ----------------
__global__ void embed_kernel(const int* __restrict__ data,
                             const float* __restrict__ we,
                             const float* __restrict__ pe,
                             float* __restrict__ h) {
    int i = blockIdx.x * blockDim.x + threadIdx.x;
    if (i >= M_ROWS * Dc) return;
    int d   = i % Dc;
    int row = i / Dc;
    int s   = row % Sc;
    int tok = data[row];
    h[i] = we[(size_t)tok * Dc + d] + pe[(size_t)s * Dc + d];
}

// ---------------- tf32 tensor-core GEMM --------------------------------------
// C[M,N] = A[M,K] @ W[N,K]^T (+bias)(+res)(relu?)   M % 128 == 0, K % 16 == 0
#define TBM 128
#define TBN 128
#define TBK 16
#define TPITCH 20   // floats; 20*4=80B row, 16B aligned, conflict-free frags

__device__ __forceinline__ uint32_t f2tf32(float f) {
    uint32_t r;
    asm("cvt.rna.tf32.f32 %0, %1;" : "=r"(r) : "f"(f));
    return r;
}

__device__ __forceinline__ void cp16(void* smem, const void* g, int srcBytes) {
    uint32_t s = (uint32_t)__cvta_generic_to_shared(smem);
    asm volatile("cp.async.cg.shared.global [%0], [%1], 16, %2;\n"
                 :: "r"(s), "l"(g), "r"(srcBytes));
}

__device__ __forceinline__ void mma_tf32(float c[4],
    uint32_t a0, uint32_t a1, uint32_t a2, uint32_t a3,
    uint32_t b0, uint32_t b1)
{
    asm volatile(
        "mma.sync.aligned.m16n8k8.row.col.f32.tf32.tf32.f32 "
        "{%0,%1,%2,%3}, {%4,%5,%6,%7}, {%8,%9}, {%0,%1,%2,%3};"
        : "+f"(c[0]), "+f"(c[1]), "+f"(c[2]), "+f"(c[3])
        : "r"(a0), "r"(a1), "r"(a2), "r"(a3), "r"(b0), "r"(b1));
}

__global__ __launch_bounds__(256) void tgemm_kernel(
    const float* __restrict__ A, const float* __restrict__ W,
    const float* __restrict__ bias, const float* __restrict__ res,
    float* __restrict__ C, int M, int N, int K, int doRelu)
{
    __shared__ __align__(16) float As[2][TBM][TPITCH];
    __shared__ __align__(16) float Bs[2][TBN][TPITCH];

    const int tid  = threadIdx.x;
    const int lane = tid & 31;
    const int warp = tid >> 5;
    const int wm   = warp >> 2;   // 0..1
    const int wn   = warp & 3;    // 0..3
    const int bm   = blockIdx.y * TBM;
    const int bn   = blockIdx.x * TBN;

    const int ldr = tid >> 2;          // 0..63
    const int kc  = (tid & 3) * 4;     // 0,4,8,12

    float acc[4][4][4];
    #pragma unroll
    for (int i = 0; i < 4; i++)
        #pragma unroll
        for (int j = 0; j < 4; j++)
            #pragma unroll
            for (int t = 0; t < 4; t++) acc[i][j][t] = 0.f;

    const int KT = K / TBK;

    // prologue: load tile 0 into buf 0
    {
        #pragma unroll
        for (int p = 0; p < 2; p++) {
            int r = ldr + p * 64;
            cp16(&As[0][r][kc], A + (size_t)(bm + r) * K + kc, 16);
        }
        #pragma unroll
        for (int p = 0; p < 2; p++) {
            int r  = ldr + p * 64;
            int gn = bn + r;
            int ok = (gn < N) ? 16 : 0;
            int gc = (gn < N) ? gn : (N - 1);
            cp16(&Bs[0][r][kc], W + (size_t)gc * K + kc, ok);
        }
        asm volatile("cp.async.commit_group;\n");
    }

    for (int t = 0; t < KT; t++) {
        asm volatile("cp.async.wait_group 0;\n");
        __syncthreads();

        if (t + 1 < KT) {
            int nb = (t + 1) & 1;
            int k0 = (t + 1) * TBK;
            #pragma unroll
            for (int p = 0; p < 2; p++) {
                int r = ldr + p * 64;
                cp16(&As[nb][r][kc], A + (size_t)(bm + r) * K + k0 + kc, 16);
            }
            #pragma unroll
            for (int p = 0; p < 2; p++) {
                int r  = ldr + p * 64;
                int gn = bn + r;
                int ok = (gn < N) ? 16 : 0;
                int gc = (gn < N) ? gn : (N - 1);
                cp16(&Bs[nb][r][kc], W + (size_t)gc * K + k0 + kc, ok);
            }
            asm volatile("cp.async.commit_group;\n");
        }

        const int buf = t & 1;
        #pragma unroll
        for (int ks = 0; ks < 2; ks++) {
            const int k8  = ks * 8;
            const int col = k8 + (lane & 3);
            const int ra  = wm * 64 + (lane >> 2);
            const int rb  = wn * 32 + (lane >> 2);

            uint32_t af[4][4], bf[4][2];
            #pragma unroll
            for (int mi = 0; mi < 4; mi++) {
                af[mi][0] = f2tf32(As[buf][ra + mi * 16    ][col]);
                af[mi][1] = f2tf32(As[buf][ra + mi * 16 + 8][col]);
                af[mi][2] = f2tf32(As[buf][ra + mi * 16    ][col + 4]);
                af[mi][3] = f2tf32(As[buf][ra + mi * 16 + 8][col + 4]);
            }
            #pragma unroll
            for (int ni = 0; ni < 4; ni++) {
                bf[ni][0] = f2tf32(Bs[buf][rb + ni * 8][col]);
                bf[ni][1] = f2tf32(Bs[buf][rb + ni * 8][col + 4]);
            }
            #pragma unroll
            for (int mi = 0; mi < 4; mi++)
                #pragma unroll
                for (int ni = 0; ni < 4; ni++)
                    mma_tf32(acc[mi][ni], af[mi][0], af[mi][1], af[mi][2], af[mi][3],
                             bf[ni][0], bf[ni][1]);
        }
        __syncthreads();
    }

    // epilogue
    const int lr = lane >> 2;
    const int lc = (lane & 3) * 2;
    #pragma unroll
    for (int mi = 0; mi < 4; mi++) {
        int r0 = bm + wm * 64 + mi * 16 + lr;
        #pragma unroll
        for (int ni = 0; ni < 4; ni++) {
            int c0 = bn + wn * 32 + ni * 8 + lc;
            if (c0 >= N) continue;
            float v0 = acc[mi][ni][0], v1 = acc[mi][ni][1];
            float v2 = acc[mi][ni][2], v3 = acc[mi][ni][3];
            if (bias) {
                float b0 = bias[c0], b1 = bias[c0 + 1];
                v0 += b0; v1 += b1; v2 += b0; v3 += b1;
            }
            if (res) {
                v0 += res[(size_t)r0 * N + c0];
                v1 += res[(size_t)r0 * N + c0 + 1];
                v2 += res[(size_t)(r0 + 8) * N + c0];
                v3 += res[(size_t)(r0 + 8) * N + c0 + 1];
            }
            if (doRelu) {
                v0 = fmaxf(v0, 0.f); v1 = fmaxf(v1, 0.f);
                v2 = fmaxf(v2, 0.f); v3 = fmaxf(v3, 0.f);
            }
            float2 w0 = make_float2(v0, v1);
            float2 w1 = make_float2(v2, v3);
            *(float2*)&C[(size_t)r0 * N + c0]       = w0;
            *(float2*)&C[(size_t)(r0 + 8) * N + c0] = w1;
        }
    }
}

// ---------------- flash attention: 64q x 64k tiles, fp32 --------------------
#define AQ 64
#define AKT 64
#define APITCH 65

extern __shared__ float attn_smem[];

__global__ __launch_bounds__(256) void fattn_kernel(
    const float* __restrict__ Q, const float* __restrict__ Kb,
    const float* __restrict__ Vb, float* __restrict__ O)
{
    float* Qs = attn_smem;                // [64][65]
    float* Ks = Qs + AQ  * APITCH;
    float* Vs = Ks + AKT * APITCH;
    float* Ps = Vs + AKT * APITCH;

    const int qt = blockIdx.x, h = blockIdx.y, b = blockIdx.z;
    const int q0 = qt * AQ;
    const int tid = threadIdx.x;
    const int tx = tid & 15, ty = tid >> 4;

    const int QSTR  = Hc * DHc;       // 512
    const int KVSTR = 2 * Hc * DHc;   // 1024

    // load Q tile (pre-scaled)
    #pragma unroll
    for (int p = 0; p < 4; p++) {
        int c = tid + p * 256;        // 1024 float4 chunks
        int r = c >> 4, d4 = (c & 15) * 4;
        float4 v = *(const float4*)(Q + (size_t)(b * Sc + q0 + r) * QSTR + h * DHc + d4);
        const float sc = 0.125f;
        Qs[r * APITCH + d4 + 0] = v.x * sc;
        Qs[r * APITCH + d4 + 1] = v.y * sc;
        Qs[r * APITCH + d4 + 2] = v.z * sc;
        Qs[r * APITCH + d4 + 3] = v.w * sc;
    }

    float acc[4][4];
    float mrow[4], lrow[4];
    #pragma unroll
    for (int i = 0; i < 4; i++) {
        mrow[i] = -1e30f; lrow[i] = 0.f;
        #pragma unroll
        for (int j = 0; j < 4; j++) acc[i][j] = 0.f;
    }

    for (int kt = 0; kt <= qt; kt++) {
        int k0 = kt * AKT;
        __syncthreads();   // Ks/Vs/Ps safe to overwrite
        #pragma unroll
        for (int p = 0; p < 4; p++) {
            int c = tid + p * 256;
            int r = c >> 4, d4 = (c & 15) * 4;
            const float* kp = Kb + (size_t)(b * Sc + k0 + r) * KVSTR + h * DHc + d4;
            const float* vp = Vb + (size_t)(b * Sc + k0 + r) * KVSTR + h * DHc + d4;
            float4 kv4 = *(const float4*)kp;
            float4 vv4 = *(const float4*)vp;
            Ks[r * APITCH + d4 + 0] = kv4.x; Ks[r * APITCH + d4 + 1] = kv4.y;
            Ks[r * APITCH + d4 + 2] = kv4.z; Ks[r * APITCH + d4 + 3] = kv4.w;
            Vs[r * APITCH + d4 + 0] = vv4.x; Vs[r * APITCH + d4 + 1] = vv4.y;
            Vs[r * APITCH + d4 + 2] = vv4.z; Vs[r * APITCH + d4 + 3] = vv4.w;
        }
        __syncthreads();

        // scores S = Qs @ Ks^T  (this thread: rows ty*4+i, cols tx*4+j)
        float s[4][4];
        #pragma unroll
        for (int i = 0; i < 4; i++)
            #pragma unroll
            for (int j = 0; j < 4; j++) s[i][j] = 0.f;

        #pragma unroll 8
        for (int d = 0; d < 64; d++) {
            float qv[4], kv[4];
            #pragma unroll
            for (int i = 0; i < 4; i++) qv[i] = Qs[(ty * 4 + i) * APITCH + d];
            #pragma unroll
            for (int j = 0; j < 4; j++) kv[j] = Ks[(tx * 4 + j) * APITCH + d];
            #pragma unroll
            for (int i = 0; i < 4; i++)
                #pragma unroll
                for (int j = 0; j < 4; j++) s[i][j] += qv[i] * kv[j];
        }

        if (kt == qt) {   // diagonal tile: causal mask (tiles aligned)
            #pragma unroll
            for (int i = 0; i < 4; i++)
                #pragma unroll
                for (int j = 0; j < 4; j++)
                    if (tx * 4 + j > ty * 4 + i) s[i][j] = -1e30f;
        }

        // online softmax, per row (16-lane row groups, xor shuffles stay in group)
        #pragma unroll
        for (int i = 0; i < 4; i++) {
            float mt = fmaxf(fmaxf(s[i][0], s[i][1]), fmaxf(s[i][2], s[i][3]));
            #pragma unroll
            for (int o = 8; o; o >>= 1) mt = fmaxf(mt, __shfl_xor_sync(0xffffffffu, mt, o));
            float mnew = fmaxf(mrow[i], mt);
            float corr = __expf(mrow[i] - mnew);
            float rs = 0.f;
            #pragma unroll
            for (int j = 0; j < 4; j++) {
                float p = __expf(s[i][j] - mnew);
                Ps[(ty * 4 + i) * APITCH + tx * 4 + j] = p;
                rs += p;
            }
            #pragma unroll
            for (int o = 8; o; o >>= 1) rs += __shfl_xor_sync(0xffffffffu, rs, o);
            lrow[i] = lrow[i] * corr + rs;
            mrow[i] = mnew;
            #pragma unroll
            for (int j = 0; j < 4; j++) acc[i][j] *= corr;
        }
        __syncthreads();

        // acc += Ps @ Vs
        #pragma unroll 8
        for (int kk = 0; kk < 64; kk++) {
            float pv[4], vv[4];
            #pragma unroll
            for (int i = 0; i < 4; i++) pv[i] = Ps[(ty * 4 + i) * APITCH + kk];
            #pragma unroll
            for (int j = 0; j < 4; j++) vv[j] = Vs[kk * APITCH + tx * 4 + j];
            #pragma unroll
            for (int i = 0; i < 4; i++)
                #pragma unroll
                for (int j = 0; j < 4; j++) acc[i][j] += pv[i] * vv[j];
        }
    }

    #pragma unroll
    for (int i = 0; i < 4; i++) {
        float inv = 1.f / lrow[i];
        #pragma unroll
        for (int j = 0; j < 4; j++)
            O[(size_t)(b * Sc + q0 + ty * 4 + i) * QSTR + h * DHc + tx * 4 + j] = acc[i][j] * inv;
    }
}

// ---------------- LayerNorm over D=512 --------------------------------------
__global__ void ln_kernel(const float* __restrict__ X, const float* __restrict__ g,
                          const float* __restrict__ bta, float* __restrict__ Y) {
    int row = blockIdx.x;
    const float* x = X + (size_t)row * Dc;
    float* y = Y + (size_t)row * Dc;
    int tid = threadIdx.x;

    float v[4];
    float sum = 0.f;
    #pragma unroll
    for (int i = 0; i < 4; i++) { v[i] = x[tid + i*128]; sum += v[i]; }

    __shared__ float red[4];
    #pragma unroll
    for (int off = 16; off; off >>= 1) sum += __shfl_xor_sync(0xffffffffu, sum, off);
    if ((tid & 31) == 0) red[tid >> 5] = sum;
    __syncthreads();
    sum = red[0] + red[1] + red[2] + red[3];
    float mean = sum * (1.f / Dc);

    float sq = 0.f;
    #pragma unroll
    for (int i = 0; i < 4; i++) { float d = v[i] - mean; sq += d * d; }
    __shared__ float red2[4];
    #pragma unroll
    for (int off = 16; off; off >>= 1) sq += __shfl_xor_sync(0xffffffffu, sq, off);
    if ((tid & 31) == 0) red2[tid >> 5] = sq;
    __syncthreads();
    sq = red2[0] + red2[1] + red2[2] + red2[3];
    float rstd = rsqrtf(sq * (1.f / Dc) + 1e-5f);

    #pragma unroll
    for (int i = 0; i < 4; i++) {
        int d = tid + i*128;
        y[d] = (v[i] - mean) * rstd * g[d] + bta[d];
    }
}

// ---------------- launch ----------------------------------------------------
extern "C" void kernel_launch(void* const* d_in, const int* in_sizes, int n_in,
                              void* d_out, int out_size) {
    const int*   data = (const int*)  d_in[0];
    const float* we   = (const float*)d_in[1];
    const float* pe   = (const float*)d_in[2];
    const float* Wq   = (const float*)d_in[3];
    const float* Wkv  = (const float*)d_in[4];
    const float* Wo   = (const float*)d_in[5];
    const float* g1   = (const float*)d_in[6];
    const float* bl1  = (const float*)d_in[7];
    const float* W1   = (const float*)d_in[8];
    const float* bf1  = (const float*)d_in[9];
    const float* W2   = (const float*)d_in[10];
    const float* bf2  = (const float*)d_in[11];
    const float* g2   = (const float*)d_in[12];
    const float* bl2  = (const float*)d_in[13];
    const float* outb = (const float*)d_in[14];
    float* out = (float*)d_out;

    float *h, *q, *kv, *ao, *tmp, *ff;
    cudaGetSymbolAddress((void**)&h,   g_h);
    cudaGetSymbolAddress((void**)&q,   g_q);
    cudaGetSymbolAddress((void**)&kv,  g_kv);
    cudaGetSymbolAddress((void**)&ao,  g_ao);
    cudaGetSymbolAddress((void**)&tmp, g_tmp);
    cudaGetSymbolAddress((void**)&ff,  g_ff);

    cudaFuncSetAttribute(fattn_kernel, cudaFuncAttributeMaxDynamicSharedMemorySize,
                         4 * AQ * APITCH * (int)sizeof(float));

    embed_kernel<<<(M_ROWS*Dc + 255)/256, 256>>>(data, we, pe, h);

    dim3 gsD (( Dc   + 127)/128, M_ROWS/128);
    dim3 gsKV((2*Dc  + 127)/128, M_ROWS/128);
    dim3 gsDI(( DIc  + 127)/128, M_ROWS/128);
    dim3 gsV (( Vc   + 127)/128, M_ROWS/128);
    dim3 gsA (Sc/AQ, Hc, Bc);
    int attn_smem_bytes = 4 * AQ * APITCH * (int)sizeof(float);

    for (int l = 0; l < Lc; l++) {
        const float* wq  = Wq  + (size_t)l * Dc * Dc;
        const float* wkv = Wkv + (size_t)l * 2 * Dc * Dc;
        const float* wo  = Wo  + (size_t)l * Dc * Dc;

        tgemm_kernel<<<gsD,  256>>>(h, wq,  nullptr, nullptr, q,  M_ROWS, Dc,   Dc, 0);
        tgemm_kernel<<<gsKV, 256>>>(h, wkv, nullptr, nullptr, kv, M_ROWS, 2*Dc, Dc, 0);

        fattn_kernel<<<gsA, 256, attn_smem_bytes>>>(q, kv, kv + Dc, ao);

        tgemm_kernel<<<gsD, 256>>>(ao, wo, nullptr, h, tmp, M_ROWS, Dc, Dc, 0);
        ln_kernel<<<M_ROWS, 128>>>(tmp, g1 + (size_t)l*Dc, bl1 + (size_t)l*Dc, h);

        tgemm_kernel<<<gsDI, 256>>>(h,  W1 + (size_t)l*DIc*Dc, bf1 + (size_t)l*DIc, nullptr, ff,  M_ROWS, DIc, Dc,  1);
        tgemm_kernel<<<gsD,  256>>>(ff, W2 + (size_t)l*Dc*DIc, bf2 + (size_t)l*Dc,  h,       tmp, M_ROWS, Dc,  DIc, 0);
        ln_kernel<<<M_ROWS, 128>>>(tmp, g2 + (size_t)l*Dc, bl2 + (size_t)l*Dc, h);
    }

    tgemm_kernel<<<gsV, 256>>>(h, we, outb, nullptr, out, M_ROWS, Vc, Dc, 0);
}

// round 3
// speedup vs baseline: 4.5786x; 1.2852x over previous
#include <cuda_runtime.h>
#include <math.h>
#include <stdint.h>

#define Bc 4
#define Sc 1024
#define Dc 512
#define Hc 8
#define DHc 64
#define DIc 2048
#define Lc 12
#define Vc 10000
#define M_ROWS (Bc*Sc)   /* 4096 */

// ---------------- scratch (no allocations allowed) ----------------
__device__ float g_h  [M_ROWS*Dc];
__device__ float g_q  [M_ROWS*Dc];
__device__ float g_kv [M_ROWS*2*Dc];
__device__ float g_ao [M_ROWS*Dc];
__device__ float g_tmp[M_ROWS*Dc];
__device__ float g_ff [M_ROWS*DIc];

// ---------------- embedding ----------------
__global__ void embed_kernel(const int* __restrict__ data,
                             const float* __restrict__ we,
                             const float* __restrict__ pe,
                             float* __restrict__ h) {
    int i = blockIdx.x * blockDim.x + threadIdx.x;
    if (i >= M_ROWS * Dc) return;
    int d   = i % Dc;
    int row = i / Dc;
    int s   = row % Sc;
    int tok = data[row];
    h[i] = we[(size_t)tok * Dc + d] + pe[(size_t)s * Dc + d];
}

// ---------------- tf32 helpers ----------------------------------------------
__device__ __forceinline__ uint32_t f2tf32(float f) {
    uint32_t r;
    asm("cvt.rna.tf32.f32 %0, %1;" : "=r"(r) : "f"(f));
    return r;
}

__device__ __forceinline__ void cp16(void* smem, const void* g, int srcBytes) {
    uint32_t s = (uint32_t)__cvta_generic_to_shared(smem);
    asm volatile("cp.async.cg.shared.global [%0], [%1], 16, %2;\n"
                 :: "r"(s), "l"(g), "r"(srcBytes));
}

__device__ __forceinline__ void mma_tf32(float c[4],
    uint32_t a0, uint32_t a1, uint32_t a2, uint32_t a3,
    uint32_t b0, uint32_t b1)
{
    asm volatile(
        "mma.sync.aligned.m16n8k8.row.col.f32.tf32.tf32.f32 "
        "{%0,%1,%2,%3}, {%4,%5,%6,%7}, {%8,%9}, {%0,%1,%2,%3};"
        : "+f"(c[0]), "+f"(c[1]), "+f"(c[2]), "+f"(c[3])
        : "r"(a0), "r"(a1), "r"(a2), "r"(a3), "r"(b0), "r"(b1));
}

// ---------------- tf32 tensor-core GEMM --------------------------------------
// C[M,N] = A[M,K] @ W[N,K]^T (+bias)(+res)(relu?)   M % 128 == 0, K % 16 == 0
#define TBM 128
#define TBN 128
#define TBK 16
#define TPITCH 20

__global__ __launch_bounds__(256) void tgemm_kernel(
    const float* __restrict__ A, const float* __restrict__ W,
    const float* __restrict__ bias, const float* __restrict__ res,
    float* __restrict__ C, int M, int N, int K, int doRelu)
{
    __shared__ __align__(16) float As[2][TBM][TPITCH];
    __shared__ __align__(16) float Bs[2][TBN][TPITCH];

    const int tid  = threadIdx.x;
    const int lane = tid & 31;
    const int warp = tid >> 5;
    const int wm   = warp >> 2;
    const int wn   = warp & 3;
    const int bm   = blockIdx.y * TBM;
    const int bn   = blockIdx.x * TBN;

    const int ldr = tid >> 2;
    const int kc  = (tid & 3) * 4;

    float acc[4][4][4];
    #pragma unroll
    for (int i = 0; i < 4; i++)
        #pragma unroll
        for (int j = 0; j < 4; j++)
            #pragma unroll
            for (int t = 0; t < 4; t++) acc[i][j][t] = 0.f;

    const int KT = K / TBK;

    {
        #pragma unroll
        for (int p = 0; p < 2; p++) {
            int r = ldr + p * 64;
            cp16(&As[0][r][kc], A + (size_t)(bm + r) * K + kc, 16);
        }
        #pragma unroll
        for (int p = 0; p < 2; p++) {
            int r  = ldr + p * 64;
            int gn = bn + r;
            int ok = (gn < N) ? 16 : 0;
            int gc = (gn < N) ? gn : (N - 1);
            cp16(&Bs[0][r][kc], W + (size_t)gc * K + kc, ok);
        }
        asm volatile("cp.async.commit_group;\n");
    }

    for (int t = 0; t < KT; t++) {
        asm volatile("cp.async.wait_group 0;\n");
        __syncthreads();

        if (t + 1 < KT) {
            int nb = (t + 1) & 1;
            int k0 = (t + 1) * TBK;
            #pragma unroll
            for (int p = 0; p < 2; p++) {
                int r = ldr + p * 64;
                cp16(&As[nb][r][kc], A + (size_t)(bm + r) * K + k0 + kc, 16);
            }
            #pragma unroll
            for (int p = 0; p < 2; p++) {
                int r  = ldr + p * 64;
                int gn = bn + r;
                int ok = (gn < N) ? 16 : 0;
                int gc = (gn < N) ? gn : (N - 1);
                cp16(&Bs[nb][r][kc], W + (size_t)gc * K + k0 + kc, ok);
            }
            asm volatile("cp.async.commit_group;\n");
        }

        const int buf = t & 1;
        #pragma unroll
        for (int ks = 0; ks < 2; ks++) {
            const int k8  = ks * 8;
            const int col = k8 + (lane & 3);
            const int ra  = wm * 64 + (lane >> 2);
            const int rb  = wn * 32 + (lane >> 2);

            uint32_t af[4][4], bf[4][2];
            #pragma unroll
            for (int mi = 0; mi < 4; mi++) {
                af[mi][0] = f2tf32(As[buf][ra + mi * 16    ][col]);
                af[mi][1] = f2tf32(As[buf][ra + mi * 16 + 8][col]);
                af[mi][2] = f2tf32(As[buf][ra + mi * 16    ][col + 4]);
                af[mi][3] = f2tf32(As[buf][ra + mi * 16 + 8][col + 4]);
            }
            #pragma unroll
            for (int ni = 0; ni < 4; ni++) {
                bf[ni][0] = f2tf32(Bs[buf][rb + ni * 8][col]);
                bf[ni][1] = f2tf32(Bs[buf][rb + ni * 8][col + 4]);
            }
            #pragma unroll
            for (int mi = 0; mi < 4; mi++)
                #pragma unroll
                for (int ni = 0; ni < 4; ni++)
                    mma_tf32(acc[mi][ni], af[mi][0], af[mi][1], af[mi][2], af[mi][3],
                             bf[ni][0], bf[ni][1]);
        }
        __syncthreads();
    }

    const int lr = lane >> 2;
    const int lc = (lane & 3) * 2;
    #pragma unroll
    for (int mi = 0; mi < 4; mi++) {
        int r0 = bm + wm * 64 + mi * 16 + lr;
        #pragma unroll
        for (int ni = 0; ni < 4; ni++) {
            int c0 = bn + wn * 32 + ni * 8 + lc;
            if (c0 >= N) continue;
            float v0 = acc[mi][ni][0], v1 = acc[mi][ni][1];
            float v2 = acc[mi][ni][2], v3 = acc[mi][ni][3];
            if (bias) {
                float b0 = bias[c0], b1 = bias[c0 + 1];
                v0 += b0; v1 += b1; v2 += b0; v3 += b1;
            }
            if (res) {
                v0 += res[(size_t)r0 * N + c0];
                v1 += res[(size_t)r0 * N + c0 + 1];
                v2 += res[(size_t)(r0 + 8) * N + c0];
                v3 += res[(size_t)(r0 + 8) * N + c0 + 1];
            }
            if (doRelu) {
                v0 = fmaxf(v0, 0.f); v1 = fmaxf(v1, 0.f);
                v2 = fmaxf(v2, 0.f); v3 = fmaxf(v3, 0.f);
            }
            *(float2*)&C[(size_t)r0 * N + c0]       = make_float2(v0, v1);
            *(float2*)&C[(size_t)(r0 + 8) * N + c0] = make_float2(v2, v3);
        }
    }
}

// ---------------- tensor-core flash attention --------------------------------
// 64q x 64k tiles, DH=64, 128 threads / 4 warps, tf32 mma for QK^T and PV.
#define AP 68   // smem pitch (floats): 68 % 32 == 4 -> conflict-free fragments

extern __shared__ float attn_smem[];

__global__ __launch_bounds__(128) void fattn_tc(
    const float* __restrict__ Q, const float* __restrict__ Kb,
    const float* __restrict__ Vb, float* __restrict__ O)
{
    float* Qs   = attn_smem;            // [64][AP]
    float* Ks   = Qs + 64 * AP;         // [64][AP]
    float* Vt   = Ks + 64 * AP;         // [64][AP]  transposed: Vt[d][k]
    float* Ss   = Vt + 64 * AP;         // [64][AP]  scores -> P
    float* rowm = Ss + 64 * AP;         // [64]
    float* rowl = rowm + 64;            // [64]
    float* rowc = rowl + 64;            // [64]

    const int qt = blockIdx.x, h = blockIdx.y, b = blockIdx.z;
    const int q0 = qt * 64;
    const int tid  = threadIdx.x;
    const int lane = tid & 31;
    const int warp = tid >> 5;          // 0..3

    const int QSTR  = Hc * DHc;         // 512
    const int KVSTR = 2 * Hc * DHc;     // 1024

    // load Q tile, pre-scaled by 1/sqrt(DH)
    #pragma unroll
    for (int p = 0; p < 8; p++) {
        int c = tid + p * 128;          // 1024 float4 chunks
        int r = c >> 4, d4 = (c & 15) * 4;
        float4 v = *(const float4*)(Q + (size_t)(b * Sc + q0 + r) * QSTR + h * DHc + d4);
        Qs[r * AP + d4 + 0] = v.x * 0.125f;
        Qs[r * AP + d4 + 1] = v.y * 0.125f;
        Qs[r * AP + d4 + 2] = v.z * 0.125f;
        Qs[r * AP + d4 + 3] = v.w * 0.125f;
    }
    if (tid < 64) { rowm[tid] = -1e30f; rowl[tid] = 0.f; }

    float o_acc[8][4];
    #pragma unroll
    for (int n = 0; n < 8; n++)
        #pragma unroll
        for (int t = 0; t < 4; t++) o_acc[n][t] = 0.f;

    const int r0 = warp * 16 + (lane >> 2);   // this thread's mma row (and +8)
    const int cq = lane & 3;                  // k-offset within fragment

    for (int kt = 0; kt <= qt; kt++) {
        const int k0 = kt * 64;
        __syncthreads();    // previous iteration's smem reads complete

        // load K tile [64][64]
        #pragma unroll
        for (int p = 0; p < 8; p++) {
            int c = tid + p * 128;
            int r = c >> 4, d4 = (c & 15) * 4;
            float4 v = *(const float4*)(Kb + (size_t)(b * Sc + k0 + r) * KVSTR + h * DHc + d4);
            Ks[r * AP + d4 + 0] = v.x; Ks[r * AP + d4 + 1] = v.y;
            Ks[r * AP + d4 + 2] = v.z; Ks[r * AP + d4 + 3] = v.w;
        }
        // load V transposed: Vt[d][k]
        #pragma unroll
        for (int p = 0; p < 32; p++) {
            int idx = tid + p * 128;          // 4096 elements
            int d = idx & 63, k = idx >> 6;
            Vt[d * AP + k] = Vb[(size_t)(b * Sc + k0 + k) * KVSTR + h * DHc + d];
        }
        __syncthreads();

        // S = Q @ K^T : warp covers rows [warp*16, +16), cols [0,64)
        float sacc[8][4];
        #pragma unroll
        for (int n = 0; n < 8; n++)
            #pragma unroll
            for (int t = 0; t < 4; t++) sacc[n][t] = 0.f;

        #pragma unroll
        for (int k8 = 0; k8 < 8; k8++) {
            int kcol = k8 * 8 + cq;
            uint32_t a0 = f2tf32(Qs[ r0      * AP + kcol]);
            uint32_t a1 = f2tf32(Qs[(r0 + 8) * AP + kcol]);
            uint32_t a2 = f2tf32(Qs[ r0      * AP + kcol + 4]);
            uint32_t a3 = f2tf32(Qs[(r0 + 8) * AP + kcol + 4]);
            #pragma unroll
            for (int n = 0; n < 8; n++) {
                int nr = n * 8 + (lane >> 2);
                uint32_t b0 = f2tf32(Ks[nr * AP + kcol]);
                uint32_t b1 = f2tf32(Ks[nr * AP + kcol + 4]);
                mma_tf32(sacc[n], a0, a1, a2, a3, b0, b1);
            }
        }

        // write scores to smem
        #pragma unroll
        for (int n = 0; n < 8; n++) {
            int c0 = n * 8 + (lane & 3) * 2;
            *(float2*)&Ss[ r0      * AP + c0] = make_float2(sacc[n][0], sacc[n][1]);
            *(float2*)&Ss[(r0 + 8) * AP + c0] = make_float2(sacc[n][2], sacc[n][3]);
        }
        __syncthreads();

        // online softmax: 2 threads per row
        {
            int row  = tid >> 1;
            int half = tid & 1;
            int cb   = half * 32;
            bool diag = (kt == qt);
            float sv[32];
            float mx = -1e30f;
            #pragma unroll
            for (int j = 0; j < 32; j++) {
                int c = cb + j;
                float s = Ss[row * AP + c];
                if (diag && c > row) s = -1e30f;
                sv[j] = s;
                mx = fmaxf(mx, s);
            }
            mx = fmaxf(mx, __shfl_xor_sync(0xffffffffu, mx, 1));
            float m_old = rowm[row];
            float mnew  = fmaxf(m_old, mx);
            float corr  = __expf(m_old - mnew);
            float sum = 0.f;
            #pragma unroll
            for (int j = 0; j < 32; j++) {
                float p = __expf(sv[j] - mnew);
                Ss[row * AP + cb + j] = p;
                sum += p;
            }
            sum += __shfl_xor_sync(0xffffffffu, sum, 1);
            if (half == 0) {
                rowl[row] = rowl[row] * corr + sum;
                rowm[row] = mnew;
                rowc[row] = corr;
            }
        }
        __syncthreads();

        // rescale O accumulators and add P @ V
        {
            float c0f = rowc[r0];
            float c1f = rowc[r0 + 8];
            #pragma unroll
            for (int n = 0; n < 8; n++) {
                o_acc[n][0] *= c0f; o_acc[n][1] *= c0f;
                o_acc[n][2] *= c1f; o_acc[n][3] *= c1f;
            }
        }
        #pragma unroll
        for (int k8 = 0; k8 < 8; k8++) {
            int kcol = k8 * 8 + cq;
            uint32_t a0 = f2tf32(Ss[ r0      * AP + kcol]);
            uint32_t a1 = f2tf32(Ss[(r0 + 8) * AP + kcol]);
            uint32_t a2 = f2tf32(Ss[ r0      * AP + kcol + 4]);
            uint32_t a3 = f2tf32(Ss[(r0 + 8) * AP + kcol + 4]);
            #pragma unroll
            for (int n = 0; n < 8; n++) {
                int nr = n * 8 + (lane >> 2);
                uint32_t b0 = f2tf32(Vt[nr * AP + kcol]);
                uint32_t b1 = f2tf32(Vt[nr * AP + kcol + 4]);
                mma_tf32(o_acc[n], a0, a1, a2, a3, b0, b1);
            }
        }
    }

    __syncthreads();
    {
        float inv0 = 1.f / rowl[r0];
        float inv1 = 1.f / rowl[r0 + 8];
        #pragma unroll
        for (int n = 0; n < 8; n++) {
            int c0 = n * 8 + (lane & 3) * 2;
            size_t o0 = (size_t)(b * Sc + q0 + r0)     * QSTR + h * DHc + c0;
            size_t o1 = (size_t)(b * Sc + q0 + r0 + 8) * QSTR + h * DHc + c0;
            *(float2*)&O[o0] = make_float2(o_acc[n][0] * inv0, o_acc[n][1] * inv0);
            *(float2*)&O[o1] = make_float2(o_acc[n][2] * inv1, o_acc[n][3] * inv1);
        }
    }
}

// ---------------- LayerNorm over D=512 --------------------------------------
__global__ void ln_kernel(const float* __restrict__ X, const float* __restrict__ g,
                          const float* __restrict__ bta, float* __restrict__ Y) {
    int row = blockIdx.x;
    const float* x = X + (size_t)row * Dc;
    float* y = Y + (size_t)row * Dc;
    int tid = threadIdx.x;

    float v[4];
    float sum = 0.f;
    #pragma unroll
    for (int i = 0; i < 4; i++) { v[i] = x[tid + i*128]; sum += v[i]; }

    __shared__ float red[4];
    #pragma unroll
    for (int off = 16; off; off >>= 1) sum += __shfl_xor_sync(0xffffffffu, sum, off);
    if ((tid & 31) == 0) red[tid >> 5] = sum;
    __syncthreads();
    sum = red[0] + red[1] + red[2] + red[3];
    float mean = sum * (1.f / Dc);

    float sq = 0.f;
    #pragma unroll
    for (int i = 0; i < 4; i++) { float d = v[i] - mean; sq += d * d; }
    __shared__ float red2[4];
    #pragma unroll
    for (int off = 16; off; off >>= 1) sq += __shfl_xor_sync(0xffffffffu, sq, off);
    if ((tid & 31) == 0) red2[tid >> 5] = sq;
    __syncthreads();
    sq = red2[0] + red2[1] + red2[2] + red2[3];
    float rstd = rsqrtf(sq * (1.f / Dc) + 1e-5f);

    #pragma unroll
    for (int i = 0; i < 4; i++) {
        int d = tid + i*128;
        y[d] = (v[i] - mean) * rstd * g[d] + bta[d];
    }
}

// ---------------- launch ----------------------------------------------------
extern "C" void kernel_launch(void* const* d_in, const int* in_sizes, int n_in,
                              void* d_out, int out_size) {
    const int*   data = (const int*)  d_in[0];
    const float* we   = (const float*)d_in[1];
    const float* pe   = (const float*)d_in[2];
    const float* Wq   = (const float*)d_in[3];
    const float* Wkv  = (const float*)d_in[4];
    const float* Wo   = (const float*)d_in[5];
    const float* g1   = (const float*)d_in[6];
    const float* bl1  = (const float*)d_in[7];
    const float* W1   = (const float*)d_in[8];
    const float* bf1  = (const float*)d_in[9];
    const float* W2   = (const float*)d_in[10];
    const float* bf2  = (const float*)d_in[11];
    const float* g2   = (const float*)d_in[12];
    const float* bl2  = (const float*)d_in[13];
    const float* outb = (const float*)d_in[14];
    float* out = (float*)d_out;

    float *h, *q, *kv, *ao, *tmp, *ff;
    cudaGetSymbolAddress((void**)&h,   g_h);
    cudaGetSymbolAddress((void**)&q,   g_q);
    cudaGetSymbolAddress((void**)&kv,  g_kv);
    cudaGetSymbolAddress((void**)&ao,  g_ao);
    cudaGetSymbolAddress((void**)&tmp, g_tmp);
    cudaGetSymbolAddress((void**)&ff,  g_ff);

    int attn_smem_bytes = (4 * 64 * AP + 3 * 64) * (int)sizeof(float);
    cudaFuncSetAttribute(fattn_tc, cudaFuncAttributeMaxDynamicSharedMemorySize,
                         attn_smem_bytes);

    embed_kernel<<<(M_ROWS*Dc + 255)/256, 256>>>(data, we, pe, h);

    dim3 gsD (( Dc   + 127)/128, M_ROWS/128);
    dim3 gsKV((2*Dc  + 127)/128, M_ROWS/128);
    dim3 gsDI(( DIc  + 127)/128, M_ROWS/128);
    dim3 gsV (( Vc   + 127)/128, M_ROWS/128);
    dim3 gsA (Sc/64, Hc, Bc);

    for (int l = 0; l < Lc; l++) {
        const float* wq  = Wq  + (size_t)l * Dc * Dc;
        const float* wkv = Wkv + (size_t)l * 2 * Dc * Dc;
        const float* wo  = Wo  + (size_t)l * Dc * Dc;

        tgemm_kernel<<<gsD,  256>>>(h, wq,  nullptr, nullptr, q,  M_ROWS, Dc,   Dc, 0);
        tgemm_kernel<<<gsKV, 256>>>(h, wkv, nullptr, nullptr, kv, M_ROWS, 2*Dc, Dc, 0);

        fattn_tc<<<gsA, 128, attn_smem_bytes>>>(q, kv, kv + Dc, ao);

        tgemm_kernel<<<gsD, 256>>>(ao, wo, nullptr, h, tmp, M_ROWS, Dc, Dc, 0);
        ln_kernel<<<M_ROWS, 128>>>(tmp, g1 + (size_t)l*Dc, bl1 + (size_t)l*Dc, h);

        tgemm_kernel<<<gsDI, 256>>>(h,  W1 + (size_t)l*DIc*Dc, bf1 + (size_t)l*DIc, nullptr, ff,  M_ROWS, DIc, Dc,  1);
        tgemm_kernel<<<gsD,  256>>>(ff, W2 + (size_t)l*Dc*DIc, bf2 + (size_t)l*Dc,  h,       tmp, M_ROWS, Dc,  DIc, 0);
        ln_kernel<<<M_ROWS, 128>>>(tmp, g2 + (size_t)l*Dc, bl2 + (size_t)l*Dc, h);
    }

    tgemm_kernel<<<gsV, 256>>>(h, we, outb, nullptr, out, M_ROWS, Vc, Dc, 0);
}